// round 9
// baseline (speedup 1.0000x reference)
#include <cuda_runtime.h>

// MultiDense: out[i,j,l] = sum_k x[i,j,k] * params[inds[i], l, k] + params[inds[i], l, 128]
// I=8192, J=32, IN_F=128, OUT_F=128.
//
// One CTA per i. Register tile 8j x 4l per thread to cut shared-memory
// access count (R8 ncu: L1=91% was the bottleneck, 1152 LDS/warp).
// Now 256 broadcast x LDS.128 + 256 W LDS.64 = 512 accesses per thread.
// Math is packed f32x2 (bit-exact fp32 pairs), rel_err = 0.

#define I_DIM 8192
#define J_DIM 32
#define IN_F  128
#define OUT_F 128
#define NODE_MASK 4095
#define PROW_SRC 129                      // params row: 128 weights + bias
#define PROW_PAD 130                      // padded row: float2-aligned, conflict-free
#define X_FLOATS (J_DIM * IN_F)           // 4096
#define W_SRC_FLOATS (OUT_F * PROW_SRC)   // 16512
#define W_PAD_FLOATS (OUT_F * PROW_PAD)   // 16640
#define XP_PAIRS (X_FLOATS / 2)           // 2048 float2
#define SMEM_BYTES (W_PAD_FLOATS * 4 + XP_PAIRS * 8)   // 66560 + 16384 = 82944

__device__ __forceinline__ unsigned long long ffma2(unsigned long long a,
                                                    unsigned long long b,
                                                    unsigned long long c)
{
    unsigned long long d;
    asm("fma.rn.f32x2 %0, %1, %2, %3;" : "=l"(d) : "l"(a), "l"(b), "l"(c));
    return d;
}

__device__ __forceinline__ unsigned long long pack2(float lo, float hi)
{
    unsigned long long d;
    asm("mov.b64 %0, {%1, %2};" : "=l"(d) : "f"(lo), "f"(hi));
    return d;
}

__global__ __launch_bounds__(128, 2)
void multidense_kernel(const float* __restrict__ x_in,
                       const int* __restrict__ inds,
                       const float* __restrict__ params,
                       float* __restrict__ out)
{
    extern __shared__ float smem[];
    float*  Ws = smem;                                            // [128][130]
    float2* Xp = reinterpret_cast<float2*>(smem + W_PAD_FLOATS);  // [16 jpairs][128]

    const int i = blockIdx.x;
    const int t = threadIdx.x;            // 0..127
    const int node = inds[i] & NODE_MASK; // int32 index, masked (can't IMA)

    // ---- stage params row with 129->130 re-stride ----
    // gidx = t + 128*r walks the source; (l,k) tracked incrementally (no div).
    // LDG coalesced; STS offsets consecutive within a warp -> conflict-free.
    {
        const float* pg = params + (size_t)node * W_SRC_FLOATS;
        int idx = t;          // source index = 129*l + k
        int k   = t;          // t <= 127 < 129, so l = 0, k = t
        int off = t;          // dest offset = 130*l + k
        #pragma unroll 4
        for (int r = 0; r < PROW_SRC; r++) {
            Ws[off] = pg[idx];
            idx += 128;
            const bool wrap = (k == 0);       // k==0 -> same l, k=128
            off += wrap ? 128 : 129;          // else l+1, k-1
            k    = wrap ? 128 : k - 1;
        }
    }

    // ---- stage x as j-paired float2: Xp[p*IN_F + k] = (x[2p][k], x[2p+1][k]) ----
    {
        const float* xg = x_in + (size_t)i * X_FLOATS;
        #pragma unroll
        for (int r = 0; r < XP_PAIRS / 128; r++) {        // 16 iters
            int idx = t + r * 128;
            int p = idx >> 7;
            int k = idx & 127;
            float a = xg[(2 * p) * IN_F + k];
            float b = xg[(2 * p + 1) * IN_F + k];
            Xp[idx] = make_float2(a, b);
        }
    }

    __syncthreads();

    // ---- compute: thread owns j-pairs [4*jb, 4*jb+4) x columns {cg+32c} ----
    const int cg = t & 31;                // column group
    const int jb = t >> 5;                // j-block (= warp id)

    unsigned long long acc[4][4];         // [jp][c]
    #pragma unroll
    for (int jp = 0; jp < 4; jp++)
        #pragma unroll
        for (int c = 0; c < 4; c++) acc[jp][c] = 0ull;

    const float* w0p = Ws + cg * PROW_PAD;                      // column cg
    // x pairs as 16B chunks: pair p at ulonglong2 index p*64 + 2*kk
    const ulonglong2* xbase = reinterpret_cast<const ulonglong2*>(Xp) + jb * 256;

    #pragma unroll 2
    for (int kk = 0; kk < IN_F / 4; kk++) {
        // W: 4 columns x 4 k as float2 loads (8B-aligned, phase-conflict-free)
        unsigned long long wq[4][4];
        #pragma unroll
        for (int c = 0; c < 4; c++) {
            const float2 wa = *reinterpret_cast<const float2*>(w0p + c * (32 * PROW_PAD) + 4 * kk);
            const float2 wb = *reinterpret_cast<const float2*>(w0p + c * (32 * PROW_PAD) + 4 * kk + 2);
            wq[c][0] = pack2(wa.x, wa.x);
            wq[c][1] = pack2(wa.y, wa.y);
            wq[c][2] = pack2(wb.x, wb.x);
            wq[c][3] = pack2(wb.y, wb.y);
        }
        // x: 4 j-pairs x 4 k (two LDS.128 broadcasts per pair)
        #pragma unroll
        for (int jp = 0; jp < 4; jp++) {
            const ulonglong2 v01 = xbase[jp * 64 + 2 * kk];
            const ulonglong2 v23 = xbase[jp * 64 + 2 * kk + 1];
            #pragma unroll
            for (int c = 0; c < 4; c++) {
                unsigned long long a = acc[jp][c];
                a = ffma2(v01.x, wq[c][0], a);
                a = ffma2(v01.y, wq[c][1], a);
                a = ffma2(v23.x, wq[c][2], a);
                a = ffma2(v23.y, wq[c][3], a);
                acc[jp][c] = a;
            }
        }
    }

    // ---- epilogue: bias + coalesced stores (lanes = consecutive l) ----
    float* og = out + (size_t)i * (J_DIM * OUT_F);
    #pragma unroll
    for (int c = 0; c < 4; c++) {
        const int l = cg + 32 * c;
        const float bias = Ws[l * PROW_PAD + 128];
        #pragma unroll
        for (int jp = 0; jp < 4; jp++) {
            float r0, r1;
            asm("mov.b64 {%0, %1}, %2;" : "=f"(r0), "=f"(r1) : "l"(acc[jp][c]));
            const int j0 = 2 * (4 * jb + jp);
            og[j0       * OUT_F + l] = r0 + bias;
            og[(j0 + 1) * OUT_F + l] = r1 + bias;
        }
    }
}

extern "C" void kernel_launch(void* const* d_in, const int* in_sizes, int n_in,
                              void* d_out, int out_size)
{
    const float* x_in   = (const float*)d_in[0];
    const int*   inds   = (const int*)d_in[1];
    const float* params = (const float*)d_in[2];
    float*       out    = (float*)d_out;

    static bool attr_set = false;
    if (!attr_set) {
        cudaFuncSetAttribute(multidense_kernel,
                             cudaFuncAttributeMaxDynamicSharedMemorySize, SMEM_BYTES);
        attr_set = true;
    }

    multidense_kernel<<<I_DIM, 128, SMEM_BYTES>>>(x_in, inds, params, out);
}